// round 8
// baseline (speedup 1.0000x reference)
#include <cuda_runtime.h>
#include <cuda_bf16.h>
#include <cstdint>

// ---------------------------------------------------------------------------
// Problem constants
// ---------------------------------------------------------------------------
#define T_STEPS   1024
#define BATCH     64
#define N_IN      256
#define N_HID     512
#define M_TOTAL   (T_STEPS * BATCH)       // 65536
#define YN        (BATCH * N_HID)         // 32768

#define GAIN_REC  0.04419417382415922f    // 1/sqrt(512)
#define DT_H      0.1f

__device__ float g_ext[(size_t)M_TOTAL * N_HID];   // inputs @ W_ih + b_ih

// ---------------------------------------------------------------------------
// Kernel A: ext = inputs @ W_ih + b_ih   (unchanged; ~0.45ms)
// ---------------------------------------------------------------------------
#define TA_M 64
#define TA_N 64
#define TA_K 32

__global__ __launch_bounds__(256) void ext_gemm_kernel(
    const float* __restrict__ A, const float* __restrict__ W,
    const float* __restrict__ bias)
{
    __shared__ float As[TA_K][TA_M + 4];
    __shared__ float Bs[TA_K][TA_N];

    const int tid = threadIdx.x;
    const int tx  = tid & 15;
    const int ty  = tid >> 4;
    const int m0  = blockIdx.y * TA_M;
    const int n0  = blockIdx.x * TA_N;

    float acc[4][4];
#pragma unroll
    for (int i = 0; i < 4; ++i)
#pragma unroll
        for (int j = 0; j < 4; ++j) acc[i][j] = 0.f;

    for (int kt = 0; kt < N_IN; kt += TA_K) {
#pragma unroll
        for (int j = 0; j < 2; ++j) {
            int f  = tid + j * 256;
            int r  = f >> 3;
            int c4 = f & 7;
            float4 v = *(const float4*)&A[(size_t)(m0 + r) * N_IN + kt + c4 * 4];
            As[c4 * 4 + 0][r] = v.x;
            As[c4 * 4 + 1][r] = v.y;
            As[c4 * 4 + 2][r] = v.z;
            As[c4 * 4 + 3][r] = v.w;
        }
#pragma unroll
        for (int j = 0; j < 2; ++j) {
            int f  = tid + j * 256;
            int r  = f >> 4;
            int c4 = f & 15;
            *(float4*)&Bs[r][c4 * 4] =
                *(const float4*)&W[(size_t)(kt + r) * N_HID + n0 + c4 * 4];
        }
        __syncthreads();
#pragma unroll
        for (int k = 0; k < TA_K; ++k) {
            float a[4], bb[4];
            *(float4*)a  = *(const float4*)&As[k][ty * 4];
            *(float4*)bb = *(const float4*)&Bs[k][tx * 4];
#pragma unroll
            for (int i = 0; i < 4; ++i)
#pragma unroll
                for (int j = 0; j < 4; ++j)
                    acc[i][j] = fmaf(a[i], bb[j], acc[i][j]);
        }
        __syncthreads();
    }

    float4 bv = *(const float4*)&bias[n0 + tx * 4];
#pragma unroll
    for (int i = 0; i < 4; ++i) {
        int m = m0 + ty * 4 + i;
        float4 o;
        o.x = acc[i][0] + bv.x;
        o.y = acc[i][1] + bv.y;
        o.z = acc[i][2] + bv.z;
        o.w = acc[i][3] + bv.w;
        *(float4*)&g_ext[(size_t)m * N_HID + n0 + tx * 4] = o;
    }
}

// ---------------------------------------------------------------------------
// Kernel B: persistent recurrence, 16 clusters x 8 CTAs, 768 threads.
//   Warps 0-15 : pure dot (wait kh-mbar -> dot -> partial -> bar.arrive).
//   Warps 16-23: pure dyn/comm (bar.sync -> reduce -> dyn -> TMA bulk S2S).
//   y exchange: 8 x 1KB cp.async.bulk shared::cta -> shared::cluster, each
//   completing 1 tx on the destination's per-source mbarrier.
// ---------------------------------------------------------------------------
#define RNT 768

// SMEM layout (float indices)
#define WS_F    0                      // W slice [k4][hl] float4: 32768 floats
#define YS_F    32768                  // 2 bufs x [src(8)][row(4)][64]: 4096 f
#define RED_F   36864                  // 2 bufs x [kh(8)][row(4)][hl(64)]: 4096
#define STAG_F  40960                  // yn staging [row*64+hl]: 256 floats
#define MBAR_F  41216                  // 16 mbarriers (128 B)
#define SMEM_R_BYTES ((MBAR_F + 32) * 4)

#define TX_BYTES 1024u                 // one bulk copy per source rank

__device__ __forceinline__ void mbar_init(uint32_t a, uint32_t cnt) {
    asm volatile("mbarrier.init.shared.b64 [%0], %1;" :: "r"(a), "r"(cnt) : "memory");
}
__device__ __forceinline__ void mbar_expect_tx(uint32_t a, uint32_t bytes) {
    asm volatile("mbarrier.arrive.expect_tx.shared.b64 _, [%0], %1;"
                 :: "r"(a), "r"(bytes) : "memory");
}
__device__ __forceinline__ void mbar_wait_parity(uint32_t a, uint32_t par) {
    asm volatile("{\n\t.reg .pred P;\n\t"
                 "WL_%=:\n\t"
                 "mbarrier.try_wait.parity.acquire.cluster.shared::cta.b64 P, [%0], %1, 0x989680;\n\t"
                 "@P bra WD_%=;\n\t"
                 "bra WL_%=;\n\t"
                 "WD_%=:\n\t}"
                 :: "r"(a), "r"(par) : "memory");
}
// 1KB bulk copy: my smem -> dest rank's smem, tx-completing dest's mbarrier
__device__ __forceinline__ void bulk_s2s(uint32_t dstLocal, uint32_t srcLocal,
                                         uint32_t mbarLocal, uint32_t rank) {
    asm volatile("{\n\t.reg .b32 rd, rm;\n\t"
                 "mapa.shared::cluster.u32 rd, %0, %3;\n\t"
                 "mapa.shared::cluster.u32 rm, %2, %3;\n\t"
                 "cp.async.bulk.shared::cluster.shared::cta.mbarrier::complete_tx::bytes "
                 "[rd], [%1], %4, [rm];\n\t}"
                 :: "r"(dstLocal), "r"(srcLocal), "r"(mbarLocal), "r"(rank),
                    "n"(TX_BYTES)
                 : "memory");
}
__device__ __forceinline__ float tanh_approx(float x) {
    float r;
    asm("tanh.approx.f32 %0, %1;" : "=f"(r) : "f"(x));
    return r;
}

__global__ void __cluster_dims__(8, 1, 1) __launch_bounds__(RNT, 1)
horn_rec7(const float* __restrict__ W_hh,
          const float* __restrict__ b_hh,
          const float* __restrict__ alpha,
          const float* __restrict__ omega,
          const float* __restrict__ gamma,
          const float* __restrict__ vvec,
          float* __restrict__ out)
{
    extern __shared__ float smem[];

    const int tid  = threadIdx.x;
    const int bg   = blockIdx.x >> 3;           // cluster id (16)
    const int rank = blockIdx.x & 7;            // h0 = rank*64
    const int h0   = rank * 64;
    const int warp = tid >> 5;
    const uint32_t smem_u32 = (uint32_t)__cvta_generic_to_shared(smem);
    const uint32_t mbar_base = smem_u32 + MBAR_F * 4;   // mbar[r][p] stride 8B

    // ---- fill W slice: ws[k4*64 + col] float4 packs a k-quad ----
    for (int idx = tid; idx < 64 * N_HID; idx += RNT) {
        int k = idx >> 6;
        int l = idx & 63;
        smem[WS_F + (k >> 2) * 256 + l * 4 + (k & 3)] =
            W_hh[(size_t)k * N_HID + h0 + l];
    }

    if (tid < 16) mbar_init(mbar_base + tid * 8, 1);
    __syncthreads();
    if (tid < 16) mbar_expect_tx(mbar_base + tid * 8, TX_BYTES);
    __syncthreads();
    asm volatile("barrier.cluster.arrive.aligned;" ::: "memory");
    asm volatile("barrier.cluster.wait.aligned;"   ::: "memory");

    if (warp < 16) {
        // =================== DOT WARPS (tid 0..511) ===================
        const int kh = tid >> 6;                // k-slice = source rank
        const int hl = tid & 63;
        const ulonglong2* wp = ((const ulonglong2*)smem) + (kh * 16) * 64 + hl;
        float* red0 = smem + RED_F + kh * 256 + hl;

        for (int t = 0; t < T_STEPS; ++t) {
            if (t > 0) {
                const int p = (t - 1) & 1;
                const uint32_t mb = mbar_base + (kh * 2 + p) * 8;
                mbar_wait_parity(mb, (unsigned)(((t - 1) >> 1) & 1));
                if ((tid & 63) == 0) mbar_expect_tx(mb, TX_BYTES);

                // y block from source rank kh: [row(4)][64] at YS + p*2048 + kh*256
                const ulonglong2* yb = ((const ulonglong2*)
                    (smem + YS_F + p * 2048)) + kh * 64;
                unsigned long long a0[4], a1[4];
#pragma unroll
                for (int r = 0; r < 4; ++r) { a0[r] = 0ull; a1[r] = 0ull; }
#pragma unroll
                for (int j = 0; j < 16; ++j) {
                    ulonglong2 wv = wp[j * 64];
#pragma unroll
                    for (int r = 0; r < 4; ++r) {
                        ulonglong2 yv = yb[r * 16 + j];
                        asm("fma.rn.f32x2 %0, %1, %2, %0;" : "+l"(a0[r]) : "l"(yv.x), "l"(wv.x));
                        asm("fma.rn.f32x2 %0, %1, %2, %0;" : "+l"(a1[r]) : "l"(yv.y), "l"(wv.y));
                    }
                }
                float* rp = red0 + (t & 1) * 2048;
#pragma unroll
                for (int r = 0; r < 4; ++r) {
                    float2 f0 = *(float2*)&a0[r];
                    float2 f1 = *(float2*)&a1[r];
                    rp[r * 64] = (f0.x + f0.y) + (f1.x + f1.y);
                }
            }
            asm volatile("bar.arrive 0, %0;" :: "n"(RNT) : "memory");
        }
        // drain final in-flight phase (y_1023 into mbar[kh][1], parity 1)
        mbar_wait_parity(mbar_base + (kh * 2 + 1) * 8, 1u);
    } else {
        // =================== DYN/COMM WARPS (tid 512..767) ===================
        const int tid2 = tid - 512;             // 0..255
        const int row  = tid2 >> 6;
        const int hl   = tid2 & 63;
        const int dh   = h0 + hl;

        const float bhh  = __ldg(&b_hh[dh]);
        const float dtal = DT_H * __ldg(&alpha[dh]);
        const float om   = __ldg(&omega[dh]);
        const float om2  = om * om;
        const float g2   = 2.f * __ldg(&gamma[dh]);
        const float vv   = __ldg(&vvec[dh]);
        const int b = bg * 4 + row;
        const float* ep = g_ext + (size_t)b * N_HID + dh;
        float*       op = out   + (size_t)b * N_HID + dh;

        float x = 0.f;
        float lin  = 0.f;                       // y + h*(-om2*x - g2*y)
        float base = GAIN_REC * bhh;            // GAIN*(bhh + vv*x)
        float ec = __ldcg((float*)ep);          // ext t
        float e1 = __ldcg((float*)(ep + YN));   // ext t+1

        for (int t = 0; t < T_STEPS; ++t) {
            asm volatile("bar.sync 0, %0;" :: "n"(RNT) : "memory");

            float acc = 0.f;
            if (t > 0) {
                const float* rp = smem + RED_F + (t & 1) * 2048 + tid2;
#pragma unroll
                for (int k = 0; k < 8; ++k)
                    acc += rp[k * 256];
            }
            float inp = ec + fmaf(GAIN_REC, acc, base);
            float th  = tanh_approx(inp);
            float yn  = fmaf(dtal, th, lin);
            float xn  = fmaf(DT_H, yn, x);
            smem[STAG_F + tid2] = yn;
            op[(size_t)t * YN] = xn;
            lin  = fmaf(DT_H, fmaf(-om2, xn, -g2 * yn), yn);
            base = GAIN_REC * fmaf(vv, xn, bhh);
            x = xn;
            ec = e1;
            e1 = __ldcg((float*)(ep + (size_t)((t + 2) & (T_STEPS - 1)) * YN));

            asm volatile("bar.sync 1, 256;" ::: "memory");

            // ---- y exchange: 8 elected threads, one 1KB bulk copy each ----
            if (tid2 < 8) {
                asm volatile("fence.proxy.async.shared::cta;" ::: "memory");
                const uint32_t src = smem_u32 + STAG_F * 4;
                const uint32_t dstLocal = smem_u32 +
                    (uint32_t)((YS_F + (t & 1) * 2048 + rank * 256) * 4);
                const uint32_t mbl = mbar_base + (rank * 2 + (t & 1)) * 8;
                bulk_s2s(dstLocal, src, mbl, (uint32_t)tid2);
            }
        }
    }

    asm volatile("barrier.cluster.arrive.aligned;" ::: "memory");
    asm volatile("barrier.cluster.wait.aligned;"   ::: "memory");
}

// ---------------------------------------------------------------------------
// Launch
// ---------------------------------------------------------------------------
extern "C" void kernel_launch(void* const* d_in, const int* in_sizes, int n_in,
                              void* d_out, int out_size)
{
    const float* inputs = (const float*)d_in[0];
    const float* W_ih   = (const float*)d_in[1];
    const float* b_ih   = (const float*)d_in[2];
    const float* W_hh   = (const float*)d_in[3];
    const float* b_hh   = (const float*)d_in[4];
    const float* alpha  = (const float*)d_in[5];
    const float* omega  = (const float*)d_in[6];
    const float* gamma  = (const float*)d_in[7];
    const float* v      = (const float*)d_in[8];
    float* out = (float*)d_out;

    (void)in_sizes; (void)n_in; (void)out_size;

    cudaFuncSetAttribute(horn_rec7,
                         cudaFuncAttributeMaxDynamicSharedMemorySize,
                         SMEM_R_BYTES);

    dim3 gA(N_HID / TA_N, M_TOTAL / TA_M);
    ext_gemm_kernel<<<gA, 256>>>(inputs, W_ih, b_ih);

    horn_rec7<<<128, RNT, SMEM_R_BYTES>>>(W_hh, b_hh, alpha, omega,
                                          gamma, v, out);
}